// round 11
// baseline (speedup 1.0000x reference)
#include <cuda_runtime.h>
#include <math.h>
#include <stdint.h>

// Problem constants
#define T_TOK 2048
#define DDIM  2048
#define NEXP  16
#define IDIM  1024
#define SIDIM 2048
#define KTOP  4

// ---------------- scratch (__device__ globals, allocation-free) ----------------
__device__ float g_h_shared[(size_t)T_TOK * SIDIM];
__device__ float g_h_moe[(size_t)T_TOK * KTOP * IDIM];
__device__ float g_y_moe[(size_t)T_TOK * KTOP * DDIM];
__device__ int   g_counts[NEXP];
__device__ int   g_rows[NEXP * T_TOK];
__device__ float g_slotw[T_TOK * KTOP];
__device__ float g_x_t[(size_t)T_TOK * DDIM];   // tf32-rounded x

// ---------------- helpers ----------------
__device__ __forceinline__ uint32_t f2tf(float f) {
    uint32_t r;
    asm("cvt.rna.tf32.f32 %0, %1;" : "=r"(r) : "f"(f));
    return r;
}
__device__ __forceinline__ uint4 cvt4(float4 v) {
    uint4 t;
    t.x = f2tf(v.x); t.y = f2tf(v.y); t.z = f2tf(v.z); t.w = f2tf(v.w);
    return t;
}
__device__ __forceinline__ void mma8(float c[4], const uint32_t a[4], const uint32_t b[2]) {
    asm volatile(
        "mma.sync.aligned.m16n8k8.row.col.f32.tf32.tf32.f32 "
        "{%0,%1,%2,%3}, {%4,%5,%6,%7}, {%8,%9}, {%0,%1,%2,%3};"
        : "+f"(c[0]), "+f"(c[1]), "+f"(c[2]), "+f"(c[3])
        : "r"(a[0]), "r"(a[1]), "r"(a[2]), "r"(a[3]), "r"(b[0]), "r"(b[1]));
}
__device__ __forceinline__ uint32_t smem_u32(const void* p) {
    uint32_t a;
    asm("{ .reg .u64 t; cvta.to.shared.u64 t, %1; cvt.u32.u64 %0, t; }" : "=r"(a) : "l"(p));
    return a;
}
__device__ __forceinline__ void cp16(uint32_t saddr, const void* gptr, uint32_t sz) {
    asm volatile("cp.async.cg.shared.global [%0], [%1], 16, %2;"
                 :: "r"(saddr), "l"(gptr), "r"(sz) : "memory");
}
#define CP_COMMIT() asm volatile("cp.async.commit_group;" ::: "memory")
#define CP_WAIT1()  asm volatile("cp.async.wait_group 1;" ::: "memory")

// smem stage: A 4096 words + B 4352 words (32 rows x 136 incl pad) = 8448 words
#define STG_WORDS 8448
#define STG_BYTES (STG_WORDS * 4)          // 33792
#define SM_BYTES  (3 * STG_BYTES)          // 101376

// ---------------- conversion kernel (x only): dst = tf32_rna(src) ----------------
__global__ void cvt_kernel(const float4* __restrict__ src, float4* __restrict__ dst, int n4) {
    const long long step = (long long)gridDim.x * 2048;
    for (long long base = (long long)blockIdx.x * 2048 + threadIdx.x; base < n4; base += step) {
        float4 v[8];
#pragma unroll
        for (int k = 0; k < 8; k++) v[k] = src[base + k * 256];
        uint4 t[8];
#pragma unroll
        for (int k = 0; k < 8; k++) t[k] = cvt4(v[k]);
#pragma unroll
        for (int k = 0; k < 8; k++) dst[base + k * 256] = *(float4*)&t[k];
    }
}

// ---------------- init + router ----------------
__global__ void init_kernel() {
    if (threadIdx.x < NEXP) g_counts[threadIdx.x] = 0;
}

__global__ void router_kernel(const float* __restrict__ x,
                              const float* __restrict__ gw,
                              const float* __restrict__ gb) {
    int wid  = threadIdx.x >> 5;
    int lane = threadIdx.x & 31;
    int t = blockIdx.x * (blockDim.x >> 5) + wid;
    if (t >= T_TOK) return;

    float acc[NEXP];
#pragma unroll
    for (int e = 0; e < NEXP; e++) acc[e] = 0.f;
    const float* xr = x + (size_t)t * DDIM;
    for (int j = lane; j < DDIM; j += 32) {
        float xv = xr[j];
#pragma unroll
        for (int e = 0; e < NEXP; e++) acc[e] += xv * gw[e * DDIM + j];
    }
#pragma unroll
    for (int e = 0; e < NEXP; e++) {
#pragma unroll
        for (int off = 16; off > 0; off >>= 1)
            acc[e] += __shfl_xor_sync(0xffffffffu, acc[e], off);
    }
    float mx = acc[0];
#pragma unroll
    for (int e = 1; e < NEXP; e++) mx = fmaxf(mx, acc[e]);
    float p[NEXP]; float sum = 0.f;
#pragma unroll
    for (int e = 0; e < NEXP; e++) { p[e] = expf(acc[e] - mx); sum += p[e]; }
    float inv = 1.f / sum;
#pragma unroll
    for (int e = 0; e < NEXP; e++) p[e] *= inv;
    float bmin = gb[0];
#pragma unroll
    for (int e = 1; e < NEXP; e++) bmin = fminf(bmin, gb[e]);
    float sel[NEXP];
#pragma unroll
    for (int e = 0; e < NEXP; e++) sel[e] = p[e] + (gb[e] - bmin);
    int idx[KTOP]; float w[KTOP]; float wsum = 0.f;
#pragma unroll
    for (int s = 0; s < KTOP; s++) {
        int best = 0; float bv = sel[0];
#pragma unroll
        for (int e = 1; e < NEXP; e++) { if (sel[e] > bv) { bv = sel[e]; best = e; } }
        idx[s] = best; w[s] = p[best]; wsum += p[best];
        sel[best] = -1e30f;
    }
    float invw = 1.f / wsum;
    if (lane == 0) {
#pragma unroll
        for (int s = 0; s < KTOP; s++) {
            int slot = t * KTOP + s;
            g_slotw[slot] = w[s] * invw;
            int pos = atomicAdd(&g_counts[idx[s]], 1);
            g_rows[idx[s] * T_TOK + pos] = slot;
        }
    }
}

// ---------------- tf32 mma.sync GEMM ----------------
// 128 threads = 4 warps (2M x 2N), warp tile 64x64, block tile 128 x N x 32.
// A: pre-rounded tf32-in-fp32 via cp.async (3-stage).
// B: RAW fp32 weights, LDG.128 -> cvt.rna.tf32 -> STS.128, staged 2 chunks ahead.
template <bool GATHER, bool SWIGLU, bool SCALE, int SHIFT, bool CVTOUT>
__global__ void __launch_bounds__(128, 2)
tgemm(const float* __restrict__ A, const float* __restrict__ Bmat,
      float* __restrict__ C, int K, int lda, int ldb, int ldc,
      long long bstride, int uoff)
{
    int n = 0x7fffffff;
    const int* rowlist = nullptr;
    const float* B = Bmat;
    if (GATHER) {
        int e = blockIdx.z;
        n = g_counts[e];
        if ((int)(blockIdx.y * 128) >= n) return;
        rowlist = g_rows + e * T_TOK;
        B = Bmat + (long long)e * bstride;
    }

    extern __shared__ uint32_t smem[];
    const uint32_t sbase = smem_u32(smem);
    const int tid = threadIdx.x;
    const int wid = tid >> 5, lane = tid & 31;
    const int gid = lane >> 2, tig = lane & 3;
    const int wm = wid & 1, wn = wid >> 1;
    const int row0 = blockIdx.y * 128;
    const int BNout = SWIGLU ? 64 : 128;
    const int c0 = blockIdx.x * BNout;

    // A staging: 8 x 16B cp.async per thread per stage
    int aoff[8]; uint32_t asz[8]; uint32_t asw[8];
#pragma unroll
    for (int i = 0; i < 8; i++) {
        int f4 = tid + i * 128;
        int m = f4 >> 3, k4 = f4 & 7;
        asw[i] = (uint32_t)(m * 32 + ((k4 ^ (m & 7)) << 2)) * 4;
        int r = row0 + m;
        if (GATHER) {
            if (r < n) { aoff[i] = (rowlist[r] >> SHIFT) * lda + k4 * 4; asz[i] = 16; }
            else       { aoff[i] = 0; asz[i] = 0; }
        } else { aoff[i] = r * lda + k4 * 4; asz[i] = 16; }
    }
    // B staging: 8 x float4 LDG->cvt->STS per thread per stage
    int boff[8]; uint32_t bsw[8];
#pragma unroll
    for (int i = 0; i < 8; i++) {
        int f4 = tid + i * 128;
        int k = f4 >> 5, n4 = f4 & 31;
        int gcol;
        if (SWIGLU) {
            int t  = n4 >> 2;
            int up = (n4 >> 1) & 1;
            int ci = (n4 & 1) * 4;
            gcol = (up ? uoff : 0) + c0 + t * 8 + ci;
        } else {
            gcol = c0 + n4 * 4;
        }
        boff[i] = k * ldb + gcol;
        bsw[i] = (uint32_t)(4096 + k * 136 + n4 * 4) * 4;
    }

    float acc[4][8][4];
#pragma unroll
    for (int mt = 0; mt < 4; mt++)
#pragma unroll
        for (int j = 0; j < 8; j++)
#pragma unroll
            for (int q = 0; q < 4; q++) acc[mt][j][q] = 0.f;

    const int NC = K / 32;

#define ISSUE_A(ch)                                                          \
    {                                                                        \
        const uint32_t sb_ = sbase + (uint32_t)((ch) % 3) * STG_BYTES;       \
        const int ka_ = (ch) * 32;                                           \
        _Pragma("unroll")                                                    \
        for (int i = 0; i < 8; i++) cp16(sb_ + asw[i], A + aoff[i] + ka_, asz[i]); \
    }
#define STAGE_B(ch)                                                          \
    {                                                                        \
        char* sb_ = (char*)smem + ((ch) % 3) * STG_BYTES;                    \
        const int kb_ = (ch) * 32 * ldb;                                     \
        _Pragma("unroll")                                                    \
        for (int i = 0; i < 8; i++) {                                        \
            float4 v_ = *(const float4*)(B + boff[i] + kb_);                 \
            uint4 t_ = cvt4(v_);                                             \
            *(uint4*)(sb_ + bsw[i]) = t_;                                    \
        }                                                                    \
    }

    ISSUE_A(0); CP_COMMIT();
    STAGE_B(0);
    ISSUE_A(1); CP_COMMIT();
    STAGE_B(1);

    for (int ch = 0; ch < NC; ch++) {
        CP_WAIT1();           // A-stage ch complete
        __syncthreads();      // drains STS; readers of ch-1 done
        if (ch + 2 < NC) {
            ISSUE_A(ch + 2); CP_COMMIT();
            STAGE_B(ch + 2);
        } else {
            CP_COMMIT();
        }

        const uint32_t* As = smem + (ch % 3) * STG_WORDS;
        const uint32_t* Bs = As + 4096;
        const int msw = gid & 7;
#pragma unroll
        for (int ks = 0; ks < 4; ks++) {
            uint32_t a[4][4];
            const int c0w = ((ks * 2) ^ msw) << 2;
            const int c1w = ((ks * 2 + 1) ^ msw) << 2;
#pragma unroll
            for (int mt = 0; mt < 4; mt++) {
                const uint32_t* ap = As + (wm * 64 + mt * 16 + gid) * 32;
                a[mt][0] = ap[c0w + tig];
                a[mt][1] = ap[256 + c0w + tig];
                a[mt][2] = ap[c1w + tig];
                a[mt][3] = ap[256 + c1w + tig];
            }
            uint32_t b[8][2];
            const uint32_t* bp = Bs + (ks * 8 + tig) * 136 + wn * 64 + gid;
#pragma unroll
            for (int j = 0; j < 8; j++) {
                b[j][0] = bp[j * 8];
                b[j][1] = bp[544 + j * 8];
            }
#pragma unroll
            for (int mt = 0; mt < 4; mt++)
#pragma unroll
                for (int j = 0; j < 8; j++)
                    mma8(acc[mt][j], a[mt], b[j]);
        }
    }
#undef ISSUE_A
#undef STAGE_B

    // ---- epilogue ----
#pragma unroll
    for (int mt = 0; mt < 4; mt++) {
#pragma unroll
        for (int h = 0; h < 2; h++) {
            int r = row0 + wm * 64 + mt * 16 + gid + h * 8;
            bool valid = GATHER ? (r < n) : true;
            if (!valid) continue;
            int crow; float scale = 1.f;
            if (GATHER) {
                int slot = rowlist[r];
                crow = slot;
                if (SCALE) scale = g_slotw[slot];
            } else crow = r;
            float* cp = C + (long long)crow * ldc;
            if (SWIGLU) {
#pragma unroll
                for (int t2 = 0; t2 < 4; t2++) {
                    float g0 = acc[mt][t2 * 2][h * 2 + 0];
                    float g1 = acc[mt][t2 * 2][h * 2 + 1];
                    float u0 = acc[mt][t2 * 2 + 1][h * 2 + 0];
                    float u1 = acc[mt][t2 * 2 + 1][h * 2 + 1];
                    float2 o;
                    o.x = g0 / (1.f + expf(-g0)) * u0;
                    o.y = g1 / (1.f + expf(-g1)) * u1;
                    if (CVTOUT) {
                        o.x = __uint_as_float(f2tf(o.x));
                        o.y = __uint_as_float(f2tf(o.y));
                    }
                    *(float2*)(cp + c0 + (wn * 4 + t2) * 8 + tig * 2) = o;
                }
            } else {
#pragma unroll
                for (int j = 0; j < 8; j++) {
                    float2 o;
                    o.x = acc[mt][j][h * 2 + 0] * scale;
                    o.y = acc[mt][j][h * 2 + 1] * scale;
                    if (CVTOUT) {
                        o.x = __uint_as_float(f2tf(o.x));
                        o.y = __uint_as_float(f2tf(o.y));
                    }
                    *(float2*)(cp + c0 + (wn * 8 + j) * 8 + tig * 2) = o;
                }
            }
        }
    }
}

// ---------------- combine ----------------
__global__ void combine_kernel(float* __restrict__ out) {
    long long i = (long long)blockIdx.x * blockDim.x + threadIdx.x;
    const long long nf4 = (long long)T_TOK * DDIM / 4;
    if (i >= nf4) return;
    long long t = i / (DDIM / 4);
    int c = (int)(i % (DDIM / 4)) * 4;
    float4 o = *(float4*)(out + t * DDIM + c);
#pragma unroll
    for (int s = 0; s < KTOP; s++) {
        const float4 y = *(const float4*)(g_y_moe + ((t * KTOP + s) * (long long)DDIM) + c);
        o.x += y.x; o.y += y.y; o.z += y.z; o.w += y.w;
    }
    *(float4*)(out + t * DDIM + c) = o;
}

// ---------------- host ----------------
static float* sym_f(const void* symbol) {
    void* p = nullptr;
    cudaGetSymbolAddress(&p, symbol);
    return (float*)p;
}

extern "C" void kernel_launch(void* const* d_in, const int* in_sizes, int n_in,
                              void* d_out, int out_size) {
    (void)in_sizes; (void)n_in; (void)out_size;
    const float* x    = (const float*)d_in[0];
    const float* gw   = (const float*)d_in[1];
    const float* gb   = (const float*)d_in[2];
    const float* wgu  = (const float*)d_in[3];
    const float* wd   = (const float*)d_in[4];
    const float* wsgu = (const float*)d_in[5];
    const float* wsd  = (const float*)d_in[6];
    float* out = (float*)d_out;

    float* h_shared = sym_f(g_h_shared);
    float* h_moe    = sym_f(g_h_moe);
    float* y_moe    = sym_f(g_y_moe);
    float* x_t      = sym_f(g_x_t);

    cudaFuncSetAttribute(tgemm<false, true,  false, 0, true >, cudaFuncAttributeMaxDynamicSharedMemorySize, SM_BYTES);
    cudaFuncSetAttribute(tgemm<false, false, false, 0, false>, cudaFuncAttributeMaxDynamicSharedMemorySize, SM_BYTES);
    cudaFuncSetAttribute(tgemm<true,  true,  false, 2, true >, cudaFuncAttributeMaxDynamicSharedMemorySize, SM_BYTES);
    cudaFuncSetAttribute(tgemm<true,  false, true,  0, false>, cudaFuncAttributeMaxDynamicSharedMemorySize, SM_BYTES);

    size_t n_x = (size_t)T_TOK * DDIM / 4;

    // Two-track fork/join (graph-capture-legal: kernel launches + event deps only).
    cudaStream_t s2 = 0;
    cudaEvent_t evFork = 0, evX = 0, evB = 0;
    cudaStreamCreateWithFlags(&s2, cudaStreamNonBlocking);
    cudaEventCreateWithFlags(&evFork, cudaEventDisableTiming);
    cudaEventCreateWithFlags(&evX,    cudaEventDisableTiming);
    cudaEventCreateWithFlags(&evB,    cudaEventDisableTiming);

    cudaEventRecord(evFork, 0);
    cudaStreamWaitEvent(s2, evFork, 0);

    // ---- Track A (default stream): x cvt + shared-expert chain ----
    cvt_kernel<<<(int)(n_x / 2048), 256>>>((const float4*)x, (float4*)x_t, (int)n_x);
    cudaEventRecord(evX, 0);
    // shared gate_up + SwiGLU: x_t @ wsgu(raw) -> h_shared (tf32-rounded)
    tgemm<false, true, false, 0, true>
        <<<dim3(SIDIM / 64, T_TOK / 128, 1), 128, SM_BYTES>>>(
            x_t, wsgu, h_shared, DDIM, DDIM, 2 * SIDIM, SIDIM, 0, SIDIM);
    // shared down: h_shared @ wsd(raw) -> out (dense write covers poison)
    tgemm<false, false, false, 0, false>
        <<<dim3(DDIM / 128, T_TOK / 128, 1), 128, SM_BYTES>>>(
            h_shared, wsd, out, SIDIM, SIDIM, DDIM, DDIM, 0, 0);

    // ---- Track B (s2): router + routed-expert chain ----
    init_kernel<<<1, 32, 0, s2>>>();
    router_kernel<<<T_TOK / 8, 256, 0, s2>>>(x, gw, gb);
    cudaStreamWaitEvent(s2, evX, 0);
    // routed gate_up + SwiGLU (gather tokens): x_t @ wgu[e](raw) -> h_moe (tf32-rounded)
    tgemm<true, true, false, 2, true>
        <<<dim3(IDIM / 64, T_TOK / 128, NEXP), 128, SM_BYTES, s2>>>(
            x_t, wgu, h_moe, DDIM, DDIM, 2 * IDIM, IDIM,
            (long long)DDIM * 2 * IDIM, IDIM);
    // routed down (gather slots, scale): h_moe @ wd[e](raw) -> y_moe
    tgemm<true, false, true, 0, false>
        <<<dim3(DDIM / 128, T_TOK / 128, NEXP), 128, SM_BYTES, s2>>>(
            h_moe, wd, y_moe, IDIM, IDIM, DDIM, DDIM,
            (long long)IDIM * DDIM, 0);
    cudaEventRecord(evB, s2);

    // ---- join on default stream ----
    cudaStreamWaitEvent(0, evB, 0);
    combine_kernel<<<(T_TOK * DDIM / 4 + 255) / 256, 256>>>(out);
    // Handles intentionally not destroyed during capture (host-side only).
}

// round 14
// speedup vs baseline: 1.0141x; 1.0141x over previous
#include <cuda_runtime.h>
#include <math.h>
#include <stdint.h>

// Problem constants
#define T_TOK 2048
#define DDIM  2048
#define NEXP  16
#define IDIM  1024
#define SIDIM 2048
#define KTOP  4

// ---------------- scratch (__device__ globals, allocation-free) ----------------
__device__ float g_h_shared[(size_t)T_TOK * SIDIM];
__device__ float g_h_moe[(size_t)T_TOK * KTOP * IDIM];
__device__ float g_y_moe[(size_t)T_TOK * KTOP * DDIM];
__device__ int   g_counts[NEXP];
__device__ int   g_rows[NEXP * T_TOK];
__device__ float g_slotw[T_TOK * KTOP];
__device__ float g_x_t[(size_t)T_TOK * DDIM];   // tf32-rounded x

// ---------------- helpers ----------------
__device__ __forceinline__ uint32_t f2tf(float f) {
    uint32_t r;
    asm("cvt.rna.tf32.f32 %0, %1;" : "=r"(r) : "f"(f));
    return r;
}
__device__ __forceinline__ uint4 cvt4(float4 v) {
    uint4 t;
    t.x = f2tf(v.x); t.y = f2tf(v.y); t.z = f2tf(v.z); t.w = f2tf(v.w);
    return t;
}
__device__ __forceinline__ void mma8(float c[4], const uint32_t a[4], const uint32_t b[2]) {
    asm volatile(
        "mma.sync.aligned.m16n8k8.row.col.f32.tf32.tf32.f32 "
        "{%0,%1,%2,%3}, {%4,%5,%6,%7}, {%8,%9}, {%0,%1,%2,%3};"
        : "+f"(c[0]), "+f"(c[1]), "+f"(c[2]), "+f"(c[3])
        : "r"(a[0]), "r"(a[1]), "r"(a[2]), "r"(a[3]), "r"(b[0]), "r"(b[1]));
}
__device__ __forceinline__ uint32_t smem_u32(const void* p) {
    uint32_t a;
    asm("{ .reg .u64 t; cvta.to.shared.u64 t, %1; cvt.u32.u64 %0, t; }" : "=r"(a) : "l"(p));
    return a;
}
__device__ __forceinline__ void cp16(uint32_t saddr, const void* gptr, uint32_t sz) {
    asm volatile("cp.async.cg.shared.global [%0], [%1], 16, %2;"
                 :: "r"(saddr), "l"(gptr), "r"(sz) : "memory");
}
#define CP_COMMIT() asm volatile("cp.async.commit_group;" ::: "memory")
#define CP_WAIT1()  asm volatile("cp.async.wait_group 1;" ::: "memory")

// smem stage: A 4096 words + B 4352 words (32 rows x 136 incl pad) = 8448 words
#define STG_WORDS 8448
#define STG_BYTES (STG_WORDS * 4)          // 33792
#define SM_BYTES  (3 * STG_BYTES)          // 101376

// ---------------- conversion kernel (x only): dst = tf32_rna(src) ----------------
__global__ void cvt_kernel(const float4* __restrict__ src, float4* __restrict__ dst, int n4) {
    const long long step = (long long)gridDim.x * 2048;
    for (long long base = (long long)blockIdx.x * 2048 + threadIdx.x; base < n4; base += step) {
        float4 v[8];
#pragma unroll
        for (int k = 0; k < 8; k++) v[k] = src[base + k * 256];
        uint4 t[8];
#pragma unroll
        for (int k = 0; k < 8; k++) t[k] = cvt4(v[k]);
#pragma unroll
        for (int k = 0; k < 8; k++) dst[base + k * 256] = *(float4*)&t[k];
    }
}

// ---------------- init + router ----------------
__global__ void init_kernel() {
    if (threadIdx.x < NEXP) g_counts[threadIdx.x] = 0;
}

__global__ void router_kernel(const float* __restrict__ x,
                              const float* __restrict__ gw,
                              const float* __restrict__ gb) {
    int wid  = threadIdx.x >> 5;
    int lane = threadIdx.x & 31;
    int t = blockIdx.x * (blockDim.x >> 5) + wid;
    if (t >= T_TOK) return;

    float acc[NEXP];
#pragma unroll
    for (int e = 0; e < NEXP; e++) acc[e] = 0.f;
    const float* xr = x + (size_t)t * DDIM;
    for (int j = lane; j < DDIM; j += 32) {
        float xv = xr[j];
#pragma unroll
        for (int e = 0; e < NEXP; e++) acc[e] += xv * gw[e * DDIM + j];
    }
#pragma unroll
    for (int e = 0; e < NEXP; e++) {
#pragma unroll
        for (int off = 16; off > 0; off >>= 1)
            acc[e] += __shfl_xor_sync(0xffffffffu, acc[e], off);
    }
    float mx = acc[0];
#pragma unroll
    for (int e = 1; e < NEXP; e++) mx = fmaxf(mx, acc[e]);
    float p[NEXP]; float sum = 0.f;
#pragma unroll
    for (int e = 0; e < NEXP; e++) { p[e] = expf(acc[e] - mx); sum += p[e]; }
    float inv = 1.f / sum;
#pragma unroll
    for (int e = 0; e < NEXP; e++) p[e] *= inv;
    float bmin = gb[0];
#pragma unroll
    for (int e = 1; e < NEXP; e++) bmin = fminf(bmin, gb[e]);
    float sel[NEXP];
#pragma unroll
    for (int e = 0; e < NEXP; e++) sel[e] = p[e] + (gb[e] - bmin);
    int idx[KTOP]; float w[KTOP]; float wsum = 0.f;
#pragma unroll
    for (int s = 0; s < KTOP; s++) {
        int best = 0; float bv = sel[0];
#pragma unroll
        for (int e = 1; e < NEXP; e++) { if (sel[e] > bv) { bv = sel[e]; best = e; } }
        idx[s] = best; w[s] = p[best]; wsum += p[best];
        sel[best] = -1e30f;
    }
    float invw = 1.f / wsum;
    if (lane == 0) {
#pragma unroll
        for (int s = 0; s < KTOP; s++) {
            int slot = t * KTOP + s;
            g_slotw[slot] = w[s] * invw;
            int pos = atomicAdd(&g_counts[idx[s]], 1);
            g_rows[idx[s] * T_TOK + pos] = slot;
        }
    }
}

// ---------------- tf32 mma.sync GEMM ----------------
// 128 threads = 4 warps (2M x 2N), warp tile 64x64, block tile 128 x N x 32.
// A: pre-rounded tf32-in-fp32 via cp.async (3-stage).
// B: RAW fp32 weights. LDG for chunk ch+2 issued BEFORE chunk ch's MMA loop
//    (latency hidden under HMMA work); cvt+STS AFTER the MMA loop; the next
//    iteration's __syncthreads drains the STS before any reader.
template <bool GATHER, bool SWIGLU, bool SCALE, int SHIFT, bool CVTOUT>
__global__ void __launch_bounds__(128, 2)
tgemm(const float* __restrict__ A, const float* __restrict__ Bmat,
      float* __restrict__ C, int K, int lda, int ldb, int ldc,
      long long bstride, int uoff)
{
    int n = 0x7fffffff;
    const int* rowlist = nullptr;
    const float* B = Bmat;
    if (GATHER) {
        int e = blockIdx.z;
        n = g_counts[e];
        if ((int)(blockIdx.y * 128) >= n) return;
        rowlist = g_rows + e * T_TOK;
        B = Bmat + (long long)e * bstride;
    }

    extern __shared__ uint32_t smem[];
    const uint32_t sbase = smem_u32(smem);
    const int tid = threadIdx.x;
    const int wid = tid >> 5, lane = tid & 31;
    const int gid = lane >> 2, tig = lane & 3;
    const int wm = wid & 1, wn = wid >> 1;
    const int row0 = blockIdx.y * 128;
    const int BNout = SWIGLU ? 64 : 128;
    const int c0 = blockIdx.x * BNout;

    // A staging: 8 x 16B cp.async per thread per stage
    int aoff[8]; uint32_t asz[8]; uint32_t asw[8];
#pragma unroll
    for (int i = 0; i < 8; i++) {
        int f4 = tid + i * 128;
        int m = f4 >> 3, k4 = f4 & 7;
        asw[i] = (uint32_t)(m * 32 + ((k4 ^ (m & 7)) << 2)) * 4;
        int r = row0 + m;
        if (GATHER) {
            if (r < n) { aoff[i] = (rowlist[r] >> SHIFT) * lda + k4 * 4; asz[i] = 16; }
            else       { aoff[i] = 0; asz[i] = 0; }
        } else { aoff[i] = r * lda + k4 * 4; asz[i] = 16; }
    }
    // B staging: 8 x float4 per thread per stage
    int boff[8]; uint32_t bsw[8];
#pragma unroll
    for (int i = 0; i < 8; i++) {
        int f4 = tid + i * 128;
        int k = f4 >> 5, n4 = f4 & 31;
        int gcol;
        if (SWIGLU) {
            int t  = n4 >> 2;
            int up = (n4 >> 1) & 1;
            int ci = (n4 & 1) * 4;
            gcol = (up ? uoff : 0) + c0 + t * 8 + ci;
        } else {
            gcol = c0 + n4 * 4;
        }
        boff[i] = k * ldb + gcol;
        bsw[i] = (uint32_t)(4096 + k * 136 + n4 * 4) * 4;
    }

    float acc[4][8][4];
#pragma unroll
    for (int mt = 0; mt < 4; mt++)
#pragma unroll
        for (int j = 0; j < 8; j++)
#pragma unroll
            for (int q = 0; q < 4; q++) acc[mt][j][q] = 0.f;

    const int NC = K / 32;

#define ISSUE_A(ch)                                                          \
    {                                                                        \
        const uint32_t sb_ = sbase + (uint32_t)((ch) % 3) * STG_BYTES;       \
        const int ka_ = (ch) * 32;                                           \
        _Pragma("unroll")                                                    \
        for (int i = 0; i < 8; i++) cp16(sb_ + asw[i], A + aoff[i] + ka_, asz[i]); \
    }
#define STAGE_B_FULL(ch)                                                     \
    {                                                                        \
        char* sb_ = (char*)smem + ((ch) % 3) * STG_BYTES;                    \
        const int kb_ = (ch) * 32 * ldb;                                     \
        _Pragma("unroll")                                                    \
        for (int i = 0; i < 8; i++) {                                        \
            float4 v_ = *(const float4*)(B + boff[i] + kb_);                 \
            uint4 t_ = cvt4(v_);                                             \
            *(uint4*)(sb_ + bsw[i]) = t_;                                    \
        }                                                                    \
    }

    ISSUE_A(0); CP_COMMIT();
    STAGE_B_FULL(0);
    ISSUE_A(1); CP_COMMIT();
    STAGE_B_FULL(1);

    for (int ch = 0; ch < NC; ch++) {
        CP_WAIT1();           // A-stage ch complete
        __syncthreads();      // drains prior STS; readers of ch-1 done

        // prefetch B (chunk ch+2) into registers BEFORE the MMA loop
        float4 vpre[8];
        const bool havePre = (ch + 2 < NC);
        if (havePre) {
            ISSUE_A(ch + 2); CP_COMMIT();
            const int kb_ = (ch + 2) * 32 * ldb;
#pragma unroll
            for (int i = 0; i < 8; i++) vpre[i] = *(const float4*)(B + boff[i] + kb_);
        } else {
            CP_COMMIT();
        }

        const uint32_t* As = smem + (ch % 3) * STG_WORDS;
        const uint32_t* Bs = As + 4096;
        const int msw = gid & 7;
#pragma unroll
        for (int ks = 0; ks < 4; ks++) {
            uint32_t a[4][4];
            const int c0w = ((ks * 2) ^ msw) << 2;
            const int c1w = ((ks * 2 + 1) ^ msw) << 2;
#pragma unroll
            for (int mt = 0; mt < 4; mt++) {
                const uint32_t* ap = As + (wm * 64 + mt * 16 + gid) * 32;
                a[mt][0] = ap[c0w + tig];
                a[mt][1] = ap[256 + c0w + tig];
                a[mt][2] = ap[c1w + tig];
                a[mt][3] = ap[256 + c1w + tig];
            }
            uint32_t b[8][2];
            const uint32_t* bp = Bs + (ks * 8 + tig) * 136 + wn * 64 + gid;
#pragma unroll
            for (int j = 0; j < 8; j++) {
                b[j][0] = bp[j * 8];
                b[j][1] = bp[544 + j * 8];
            }
#pragma unroll
            for (int mt = 0; mt < 4; mt++)
#pragma unroll
                for (int j = 0; j < 8; j++)
                    mma8(acc[mt][j], a[mt], b[j]);
        }

        // cvt + STS for chunk ch+2 AFTER the MMA loop (LDG latency was hidden)
        if (havePre) {
            char* sb_ = (char*)smem + ((ch + 2) % 3) * STG_BYTES;
#pragma unroll
            for (int i = 0; i < 8; i++) {
                uint4 t_ = cvt4(vpre[i]);
                *(uint4*)(sb_ + bsw[i]) = t_;
            }
        }
    }
#undef ISSUE_A
#undef STAGE_B_FULL

    // ---- epilogue ----
#pragma unroll
    for (int mt = 0; mt < 4; mt++) {
#pragma unroll
        for (int h = 0; h < 2; h++) {
            int r = row0 + wm * 64 + mt * 16 + gid + h * 8;
            bool valid = GATHER ? (r < n) : true;
            if (!valid) continue;
            int crow; float scale = 1.f;
            if (GATHER) {
                int slot = rowlist[r];
                crow = slot;
                if (SCALE) scale = g_slotw[slot];
            } else crow = r;
            float* cp = C + (long long)crow * ldc;
            if (SWIGLU) {
#pragma unroll
                for (int t2 = 0; t2 < 4; t2++) {
                    float g0 = acc[mt][t2 * 2][h * 2 + 0];
                    float g1 = acc[mt][t2 * 2][h * 2 + 1];
                    float u0 = acc[mt][t2 * 2 + 1][h * 2 + 0];
                    float u1 = acc[mt][t2 * 2 + 1][h * 2 + 1];
                    float2 o;
                    o.x = g0 / (1.f + expf(-g0)) * u0;
                    o.y = g1 / (1.f + expf(-g1)) * u1;
                    if (CVTOUT) {
                        o.x = __uint_as_float(f2tf(o.x));
                        o.y = __uint_as_float(f2tf(o.y));
                    }
                    *(float2*)(cp + c0 + (wn * 4 + t2) * 8 + tig * 2) = o;
                }
            } else {
#pragma unroll
                for (int j = 0; j < 8; j++) {
                    float2 o;
                    o.x = acc[mt][j][h * 2 + 0] * scale;
                    o.y = acc[mt][j][h * 2 + 1] * scale;
                    if (CVTOUT) {
                        o.x = __uint_as_float(f2tf(o.x));
                        o.y = __uint_as_float(f2tf(o.y));
                    }
                    *(float2*)(cp + c0 + (wn * 8 + j) * 8 + tig * 2) = o;
                }
            }
        }
    }
}

// ---------------- combine ----------------
__global__ void combine_kernel(float* __restrict__ out) {
    long long i = (long long)blockIdx.x * blockDim.x + threadIdx.x;
    const long long nf4 = (long long)T_TOK * DDIM / 4;
    if (i >= nf4) return;
    long long t = i / (DDIM / 4);
    int c = (int)(i % (DDIM / 4)) * 4;
    float4 o = *(float4*)(out + t * DDIM + c);
#pragma unroll
    for (int s = 0; s < KTOP; s++) {
        const float4 y = *(const float4*)(g_y_moe + ((t * KTOP + s) * (long long)DDIM) + c);
        o.x += y.x; o.y += y.y; o.z += y.z; o.w += y.w;
    }
    *(float4*)(out + t * DDIM + c) = o;
}

// ---------------- host ----------------
static float* sym_f(const void* symbol) {
    void* p = nullptr;
    cudaGetSymbolAddress(&p, symbol);
    return (float*)p;
}

extern "C" void kernel_launch(void* const* d_in, const int* in_sizes, int n_in,
                              void* d_out, int out_size) {
    (void)in_sizes; (void)n_in; (void)out_size;
    const float* x    = (const float*)d_in[0];
    const float* gw   = (const float*)d_in[1];
    const float* gb   = (const float*)d_in[2];
    const float* wgu  = (const float*)d_in[3];
    const float* wd   = (const float*)d_in[4];
    const float* wsgu = (const float*)d_in[5];
    const float* wsd  = (const float*)d_in[6];
    float* out = (float*)d_out;

    float* h_shared = sym_f(g_h_shared);
    float* h_moe    = sym_f(g_h_moe);
    float* y_moe    = sym_f(g_y_moe);
    float* x_t      = sym_f(g_x_t);

    cudaFuncSetAttribute(tgemm<false, true,  false, 0, true >, cudaFuncAttributeMaxDynamicSharedMemorySize, SM_BYTES);
    cudaFuncSetAttribute(tgemm<false, false, false, 0, false>, cudaFuncAttributeMaxDynamicSharedMemorySize, SM_BYTES);
    cudaFuncSetAttribute(tgemm<true,  true,  false, 2, true >, cudaFuncAttributeMaxDynamicSharedMemorySize, SM_BYTES);
    cudaFuncSetAttribute(tgemm<true,  false, true,  0, false>, cudaFuncAttributeMaxDynamicSharedMemorySize, SM_BYTES);

    size_t n_x = (size_t)T_TOK * DDIM / 4;

    // Two-track fork/join (graph-capture-legal: kernel launches + event deps only).
    cudaStream_t s2 = 0;
    cudaEvent_t evFork = 0, evX = 0, evB = 0;
    cudaStreamCreateWithFlags(&s2, cudaStreamNonBlocking);
    cudaEventCreateWithFlags(&evFork, cudaEventDisableTiming);
    cudaEventCreateWithFlags(&evX,    cudaEventDisableTiming);
    cudaEventCreateWithFlags(&evB,    cudaEventDisableTiming);

    cudaEventRecord(evFork, 0);
    cudaStreamWaitEvent(s2, evFork, 0);

    // ---- Track A (default stream): x cvt + shared-expert chain ----
    cvt_kernel<<<(int)(n_x / 2048), 256>>>((const float4*)x, (float4*)x_t, (int)n_x);
    cudaEventRecord(evX, 0);
    // shared gate_up + SwiGLU: x_t @ wsgu(raw) -> h_shared (tf32-rounded)
    tgemm<false, true, false, 0, true>
        <<<dim3(SIDIM / 64, T_TOK / 128, 1), 128, SM_BYTES>>>(
            x_t, wsgu, h_shared, DDIM, DDIM, 2 * SIDIM, SIDIM, 0, SIDIM);
    // shared down: h_shared @ wsd(raw) -> out (dense write covers poison)
    tgemm<false, false, false, 0, false>
        <<<dim3(DDIM / 128, T_TOK / 128, 1), 128, SM_BYTES>>>(
            h_shared, wsd, out, SIDIM, SIDIM, DDIM, DDIM, 0, 0);

    // ---- Track B (s2): router + routed-expert chain ----
    init_kernel<<<1, 32, 0, s2>>>();
    router_kernel<<<T_TOK / 8, 256, 0, s2>>>(x, gw, gb);
    cudaStreamWaitEvent(s2, evX, 0);
    // routed gate_up + SwiGLU (gather tokens): x_t @ wgu[e](raw) -> h_moe (tf32-rounded)
    tgemm<true, true, false, 2, true>
        <<<dim3(IDIM / 64, T_TOK / 128, NEXP), 128, SM_BYTES, s2>>>(
            x_t, wgu, h_moe, DDIM, DDIM, 2 * IDIM, IDIM,
            (long long)DDIM * 2 * IDIM, IDIM);
    // routed down (gather slots, scale): h_moe @ wd[e](raw) -> y_moe
    tgemm<true, false, true, 0, false>
        <<<dim3(DDIM / 128, T_TOK / 128, NEXP), 128, SM_BYTES, s2>>>(
            h_moe, wd, y_moe, IDIM, IDIM, DDIM, DDIM,
            (long long)IDIM * DDIM, 0);
    cudaEventRecord(evB, s2);

    // ---- join on default stream ----
    cudaStreamWaitEvent(0, evB, 0);
    combine_kernel<<<(T_TOK * DDIM / 4 + 255) / 256, 256>>>(out);
    // Handles intentionally not destroyed during capture (host-side only).
}